// round 1
// baseline (speedup 1.0000x reference)
#include <cuda_runtime.h>
#include <math.h>

#define Bb 16
#define Tt 2048
#define Hh 512
#define Kk 15
#define BT (Bb*Tt)

// ---------------- scratch (__device__ globals; no allocations allowed) ----------------
__device__ float d_g[(size_t)BT*Hh];   // GLU output (B,T,H)  = 64MB
__device__ float d_alphas[BT];
__device__ float d_weff[Hh];
__device__ float d_beff;
__device__ int   d_nfires[Bb];
__device__ int   d_fire_t[BT];
__device__ float d_dist[BT];
__device__ float d_remain[BT];
__device__ float d_ptn[Bb];

__device__ __forceinline__ float sigm(float v){ return 1.0f/(1.0f + expf(-v)); }

__device__ __forceinline__ float wred(float v){
    #pragma unroll
    for (int o = 16; o > 0; o >>= 1) v += __shfl_down_sync(0xffffffffu, v, o);
    return v;
}

// ---------------- kernel 0: fold pw2 + lin into a single H-vector ----------------
__global__ void weff_kernel(const float* __restrict__ pw2_w, const float* __restrict__ pw2_b,
                            const float* __restrict__ lin_w, const float* __restrict__ lin_b)
{
    int h = threadIdx.x;  // 512 threads
    float s = 0.0f;
    for (int o = 0; o < Hh; o++) s = fmaf(lin_w[o], pw2_w[(size_t)o*Hh + h], s);
    d_weff[h] = s;
    if (h == 0) {
        float bb = lin_b[0];
        for (int o = 0; o < Hh; o++) bb = fmaf(lin_w[o], pw2_b[o], bb);
        d_beff = bb;
    }
}

// ---------------- kernel 1: fp32 GEMM (x @ pw1_w^T) fused with GLU ----------------
// M = 32768, K = 512, per output channel c we need weight rows c and c+H.
// Block tile 128(M) x 64(C), 256 threads, per-thread 8x4 micro-tile with two accum banks.
__launch_bounds__(256)
__global__ void gemm_glu_kernel(const float* __restrict__ x, const float* __restrict__ w,
                                const float* __restrict__ bias)
{
    __shared__ float xs[16][132];   // [k][m], padded (132 = mult of 4 floats, bank-spread)
    __shared__ float was[16][68];   // [k][c] value-half weights
    __shared__ float wbs[16][68];   // [k][c] gate-half weights

    const int tid = threadIdx.x;
    const int tx = tid & 15;        // col group (4 channels)
    const int ty = tid >> 4;        // row group (8 rows)
    const int m0 = blockIdx.x * 128;
    const int c0 = blockIdx.y * 64;

    float acc_a[8][4];
    float acc_b[8][4];
    #pragma unroll
    for (int i = 0; i < 8; i++)
        #pragma unroll
        for (int jj = 0; jj < 4; jj++) { acc_a[i][jj] = 0.0f; acc_b[i][jj] = 0.0f; }

    for (int k0 = 0; k0 < Hh; k0 += 16) {
        __syncthreads();
        // x tile: 128 rows x 16 k = 512 float4s, 2 per thread
        {
            int f = tid;
            #pragma unroll
            for (int q = 0; q < 2; q++, f += 256) {
                int m  = f >> 2;
                int kq = f & 3;
                float4 v = *(const float4*)(x + (size_t)(m0 + m)*Hh + k0 + kq*4);
                xs[kq*4+0][m] = v.x; xs[kq*4+1][m] = v.y;
                xs[kq*4+2][m] = v.z; xs[kq*4+3][m] = v.w;
            }
        }
        // weight tiles: 64 channels x 16 k per half
        {
            int c  = tid >> 2;
            int kq = tid & 3;
            float4 va = *(const float4*)(w + (size_t)(c0 + c)*Hh      + k0 + kq*4);
            float4 vb = *(const float4*)(w + (size_t)(c0 + c + Hh)*Hh + k0 + kq*4);
            was[kq*4+0][c]=va.x; was[kq*4+1][c]=va.y; was[kq*4+2][c]=va.z; was[kq*4+3][c]=va.w;
            wbs[kq*4+0][c]=vb.x; wbs[kq*4+1][c]=vb.y; wbs[kq*4+2][c]=vb.z; wbs[kq*4+3][c]=vb.w;
        }
        __syncthreads();
        #pragma unroll
        for (int kk = 0; kk < 16; kk++) {
            float4 a0 = *(const float4*)&xs[kk][ty*8];
            float4 a1 = *(const float4*)&xs[kk][ty*8+4];
            float4 wa = *(const float4*)&was[kk][tx*4];
            float4 wb = *(const float4*)&wbs[kk][tx*4];
            float av[8]  = {a0.x,a0.y,a0.z,a0.w,a1.x,a1.y,a1.z,a1.w};
            float wav[4] = {wa.x,wa.y,wa.z,wa.w};
            float wbv[4] = {wb.x,wb.y,wb.z,wb.w};
            #pragma unroll
            for (int i = 0; i < 8; i++)
                #pragma unroll
                for (int jj = 0; jj < 4; jj++) {
                    acc_a[i][jj] = fmaf(av[i], wav[jj], acc_a[i][jj]);
                    acc_b[i][jj] = fmaf(av[i], wbv[jj], acc_b[i][jj]);
                }
        }
    }

    float ba[4], bg[4];
    #pragma unroll
    for (int jj = 0; jj < 4; jj++) {
        ba[jj] = bias[c0 + tx*4 + jj];
        bg[jj] = bias[Hh + c0 + tx*4 + jj];
    }
    #pragma unroll
    for (int i = 0; i < 8; i++) {
        int m = m0 + ty*8 + i;
        float4 o;
        o.x = (acc_a[i][0] + ba[0]) * sigm(acc_b[i][0] + bg[0]);
        o.y = (acc_a[i][1] + ba[1]) * sigm(acc_b[i][1] + bg[1]);
        o.z = (acc_a[i][2] + ba[2]) * sigm(acc_b[i][2] + bg[2]);
        o.w = (acc_a[i][3] + ba[3]) * sigm(acc_b[i][3] + bg[3]);
        *(float4*)(d_g + (size_t)m*Hh + c0 + tx*4) = o;
    }
}

// ---------------- kernel 2: depthwise conv + LN + swish + folded pw2/lin -> alphas ----------------
// Block = (T-strip of 64) x batch, 512 threads (one per channel), register sliding window.
__launch_bounds__(512)
__global__ void conv_ln_logit_kernel(const float* __restrict__ dw_w, const float* __restrict__ dw_b,
                                     const float* __restrict__ ln_g, const float* __restrict__ ln_b,
                                     const int* __restrict__ x_lens)
{
    const int ch = threadIdx.x;
    const int b  = blockIdx.y;
    const int t0 = blockIdx.x * 64;
    const int lane = ch & 31, wid = ch >> 5;
    __shared__ float r1[16], r2[16], r3s[16];

    float wk[15];
    #pragma unroll
    for (int k = 0; k < 15; k++) wk[k] = dw_w[ch*Kk + k];
    const float bias = dw_b[ch];
    const float gam  = ln_g[ch];
    const float bet  = ln_b[ch];
    const float weff = d_weff[ch];
    const float beff = d_beff;
    const int   len  = x_lens[b];

    const float* gb = d_g + (size_t)b*Tt*Hh + ch;

    float win[15];
    #pragma unroll
    for (int k = 0; k < 14; k++) {
        int tg = t0 - 14 + k;
        win[k] = (tg >= 0) ? gb[(size_t)tg*Hh] : 0.0f;
    }

    for (int t = 0; t < 64; t++) {
        win[14] = gb[(size_t)(t0 + t)*Hh];
        float c = bias;
        #pragma unroll
        for (int k = 0; k < 15; k++) c = fmaf(win[k], wk[k], c);
        #pragma unroll
        for (int k = 0; k < 14; k++) win[k] = win[k+1];

        // block reduce sum & sumsq
        float s1 = wred(c);
        float s2 = wred(c*c);
        if (lane == 0) { r1[wid] = s1; r2[wid] = s2; }
        __syncthreads();
        if (wid == 0) {
            float a  = (lane < 16) ? r1[lane] : 0.0f;
            float d2 = (lane < 16) ? r2[lane] : 0.0f;
            a  = wred(a);
            d2 = wred(d2);
            if (lane == 0) { r1[0] = a; r2[0] = d2; }
        }
        __syncthreads();
        float mean = r1[0] * (1.0f/512.0f);
        float var  = r2[0] * (1.0f/512.0f) - mean*mean;
        float y  = (c - mean) * rsqrtf(var + 1e-5f) * gam + bet;
        float sw = y * sigm(y);
        float p  = wred(sw * weff);
        if (lane == 0) r3s[wid] = p;
        __syncthreads();
        if (wid == 0) {
            float a = (lane < 16) ? r3s[lane] : 0.0f;
            a = wred(a);
            if (lane == 0 && ch == 0) {
                float logit = a + beff;
                int tg = t0 + t;
                d_alphas[b*Tt + tg] = (tg < len) ? sigm(logit) : 0.0f;
            }
        }
        __syncthreads();
    }
}

// ---------------- kernel 3: per-batch serial CIF scan (exact reference arithmetic) ----------------
__global__ void scan_kernel()
{
    __shared__ float sa[Tt];  // 8KB
    const int b = blockIdx.x;
    for (int i = threadIdx.x; i < Tt; i += blockDim.x) sa[i] = d_alphas[b*Tt + i];
    __syncthreads();
    if (threadIdx.x == 0) {
        float integ = 0.0f, psum = 0.0f;
        int j = 0;
        for (int t = 0; t < Tt; t++) {
            float a = sa[t];
            psum += a;
            float dist = 1.0f - integ;   // FIRE_TH - integrate (pre-add)
            integ = integ + a;           // same op order as reference
            if (integ >= 1.0f) {
                d_fire_t[b*Tt + j] = t;
                d_dist  [b*Tt + j] = dist;
                d_remain[b*Tt + j] = a - dist;
                integ -= 1.0f;
                j++;
            }
        }
        d_nfires[b] = j;
        d_ptn[b] = psum;
    }
}

// ---------------- kernel 4: write all outputs (fired rows, token counts, flipped rows) ----------------
// Every output element written exactly once (d_out is poisoned).
__launch_bounds__(128)
__global__ void output_kernel(const float* __restrict__ x, float* __restrict__ out)
{
    const int b   = blockIdx.y;
    const int j   = blockIdx.x;
    const int tid = threadIdx.x;     // 128 threads, 4 channels each
    float* outF = out;
    float* outP = out + (size_t)Bb*Tt*Hh;
    float* outR = outP + Bb;

    if (j == 0 && tid == 0) outP[b] = d_ptn[b];

    float4 acc = make_float4(0.0f, 0.0f, 0.0f, 0.0f);
    const int nf = d_nfires[b];

    if (j < nf) {
        const float* xb = x + (size_t)b*Tt*Hh + tid*4;
        const int tEnd = d_fire_t[b*Tt + j];
        int t;
        if (j > 0) {
            int   tPrev = d_fire_t[b*Tt + j - 1];
            float wl    = d_remain[b*Tt + j - 1];
            float4 v = *(const float4*)(xb + (size_t)tPrev*Hh);
            acc.x = wl*v.x; acc.y = wl*v.y; acc.z = wl*v.z; acc.w = wl*v.w;
            t = tPrev + 1;
        } else {
            t = 0;
        }
        for (; t < tEnd; t++) {
            float w = d_alphas[b*Tt + t];
            float4 v = *(const float4*)(xb + (size_t)t*Hh);
            acc.x = fmaf(w, v.x, acc.x); acc.y = fmaf(w, v.y, acc.y);
            acc.z = fmaf(w, v.z, acc.z); acc.w = fmaf(w, v.w, acc.w);
        }
        float wd = d_dist[b*Tt + j];
        float4 v = *(const float4*)(xb + (size_t)tEnd*Hh);
        acc.x = fmaf(wd, v.x, acc.x); acc.y = fmaf(wd, v.y, acc.y);
        acc.z = fmaf(wd, v.z, acc.z); acc.w = fmaf(wd, v.w, acc.w);
    }

    *(float4*)(outF + ((size_t)b*Tt + j)*Hh + tid*4) = acc;
    // flipped along H: element ch -> H-1-ch
    *(float4*)(outR + ((size_t)b*Tt + j)*Hh + (Hh - 4 - tid*4)) =
        make_float4(acc.w, acc.z, acc.y, acc.x);
}

// ---------------- launch ----------------
extern "C" void kernel_launch(void* const* d_in, const int* in_sizes, int n_in,
                              void* d_out, int out_size)
{
    const float* x      = (const float*)d_in[0];
    const int*   x_lens = (const int*)  d_in[1];
    const float* pw1_w  = (const float*)d_in[2];
    const float* pw1_b  = (const float*)d_in[3];
    const float* dw_w   = (const float*)d_in[4];
    const float* dw_b   = (const float*)d_in[5];
    const float* ln_g   = (const float*)d_in[6];
    const float* ln_b   = (const float*)d_in[7];
    const float* pw2_w  = (const float*)d_in[8];
    const float* pw2_b  = (const float*)d_in[9];
    const float* lin_w  = (const float*)d_in[10];
    const float* lin_b  = (const float*)d_in[11];
    float* out = (float*)d_out;

    weff_kernel<<<1, Hh>>>(pw2_w, pw2_b, lin_w, lin_b);
    gemm_glu_kernel<<<dim3(BT/128, Hh/64), 256>>>(x, pw1_w, pw1_b);
    conv_ln_logit_kernel<<<dim3(Tt/64, Bb), Hh>>>(dw_w, dw_b, ln_g, ln_b, x_lens);
    scan_kernel<<<Bb, 256>>>();
    output_kernel<<<dim3(Tt, Bb), 128>>>(x, out);
}

// round 2
// speedup vs baseline: 1.0005x; 1.0005x over previous
#include <cuda_runtime.h>
#include <math.h>

#define Bb 16
#define Tt 2048
#define Hh 512
#define Kk 15
#define BT (Bb*Tt)

// ---------------- scratch (__device__ globals; no allocations allowed) ----------------
__device__ float d_g[(size_t)BT*Hh];   // GLU output (B,T,H)  = 64MB
__device__ float d_alphas[BT];
__device__ float d_weff[Hh];
__device__ float d_beff;
__device__ int   d_nfires[Bb];
__device__ int   d_fire_t[BT];
__device__ float d_dist[BT];
__device__ float d_remain[BT];
__device__ float d_ptn[Bb];

__device__ __forceinline__ float sigm(float v){ return 1.0f/(1.0f + expf(-v)); }

__device__ __forceinline__ float wred(float v){
    #pragma unroll
    for (int o = 16; o > 0; o >>= 1) v += __shfl_down_sync(0xffffffffu, v, o);
    return v;
}

// ---------------- kernel 0: fold pw2 + lin into a single H-vector ----------------
__global__ void weff_kernel(const float* __restrict__ pw2_w, const float* __restrict__ pw2_b,
                            const float* __restrict__ lin_w, const float* __restrict__ lin_b)
{
    int h = threadIdx.x;  // 512 threads
    float s = 0.0f;
    for (int o = 0; o < Hh; o++) s = fmaf(lin_w[o], pw2_w[(size_t)o*Hh + h], s);
    d_weff[h] = s;
    if (h == 0) {
        float bb = lin_b[0];
        for (int o = 0; o < Hh; o++) bb = fmaf(lin_w[o], pw2_b[o], bb);
        d_beff = bb;
    }
}

// ---------------- kernel 1: fp32 GEMM (x @ pw1_w^T) fused with GLU ----------------
// M = 32768, K = 512, per output channel c we need weight rows c and c+H.
// Block tile 128(M) x 64(C), 256 threads, per-thread 8x4 micro-tile with two accum banks.
__launch_bounds__(256)
__global__ void gemm_glu_kernel(const float* __restrict__ x, const float* __restrict__ w,
                                const float* __restrict__ bias)
{
    __shared__ float xs[16][132];   // [k][m], padded (132 = mult of 4 floats, bank-spread)
    __shared__ float was[16][68];   // [k][c] value-half weights
    __shared__ float wbs[16][68];   // [k][c] gate-half weights

    const int tid = threadIdx.x;
    const int tx = tid & 15;        // col group (4 channels)
    const int ty = tid >> 4;        // row group (8 rows)
    const int m0 = blockIdx.x * 128;
    const int c0 = blockIdx.y * 64;

    float acc_a[8][4];
    float acc_b[8][4];
    #pragma unroll
    for (int i = 0; i < 8; i++)
        #pragma unroll
        for (int jj = 0; jj < 4; jj++) { acc_a[i][jj] = 0.0f; acc_b[i][jj] = 0.0f; }

    for (int k0 = 0; k0 < Hh; k0 += 16) {
        __syncthreads();
        // x tile: 128 rows x 16 k = 512 float4s, 2 per thread
        {
            int f = tid;
            #pragma unroll
            for (int q = 0; q < 2; q++, f += 256) {
                int m  = f >> 2;
                int kq = f & 3;
                float4 v = *(const float4*)(x + (size_t)(m0 + m)*Hh + k0 + kq*4);
                xs[kq*4+0][m] = v.x; xs[kq*4+1][m] = v.y;
                xs[kq*4+2][m] = v.z; xs[kq*4+3][m] = v.w;
            }
        }
        // weight tiles: 64 channels x 16 k per half
        {
            int c  = tid >> 2;
            int kq = tid & 3;
            float4 va = *(const float4*)(w + (size_t)(c0 + c)*Hh      + k0 + kq*4);
            float4 vb = *(const float4*)(w + (size_t)(c0 + c + Hh)*Hh + k0 + kq*4);
            was[kq*4+0][c]=va.x; was[kq*4+1][c]=va.y; was[kq*4+2][c]=va.z; was[kq*4+3][c]=va.w;
            wbs[kq*4+0][c]=vb.x; wbs[kq*4+1][c]=vb.y; wbs[kq*4+2][c]=vb.z; wbs[kq*4+3][c]=vb.w;
        }
        __syncthreads();
        #pragma unroll
        for (int kk = 0; kk < 16; kk++) {
            float4 a0 = *(const float4*)&xs[kk][ty*8];
            float4 a1 = *(const float4*)&xs[kk][ty*8+4];
            float4 wa = *(const float4*)&was[kk][tx*4];
            float4 wb = *(const float4*)&wbs[kk][tx*4];
            float av[8]  = {a0.x,a0.y,a0.z,a0.w,a1.x,a1.y,a1.z,a1.w};
            float wav[4] = {wa.x,wa.y,wa.z,wa.w};
            float wbv[4] = {wb.x,wb.y,wb.z,wb.w};
            #pragma unroll
            for (int i = 0; i < 8; i++)
                #pragma unroll
                for (int jj = 0; jj < 4; jj++) {
                    acc_a[i][jj] = fmaf(av[i], wav[jj], acc_a[i][jj]);
                    acc_b[i][jj] = fmaf(av[i], wbv[jj], acc_b[i][jj]);
                }
        }
    }

    float ba[4], bg[4];
    #pragma unroll
    for (int jj = 0; jj < 4; jj++) {
        ba[jj] = bias[c0 + tx*4 + jj];
        bg[jj] = bias[Hh + c0 + tx*4 + jj];
    }
    #pragma unroll
    for (int i = 0; i < 8; i++) {
        int m = m0 + ty*8 + i;
        float4 o;
        o.x = (acc_a[i][0] + ba[0]) * sigm(acc_b[i][0] + bg[0]);
        o.y = (acc_a[i][1] + ba[1]) * sigm(acc_b[i][1] + bg[1]);
        o.z = (acc_a[i][2] + ba[2]) * sigm(acc_b[i][2] + bg[2]);
        o.w = (acc_a[i][3] + ba[3]) * sigm(acc_b[i][3] + bg[3]);
        *(float4*)(d_g + (size_t)m*Hh + c0 + tx*4) = o;
    }
}

// ---------------- kernel 2: depthwise conv + LN + swish + folded pw2/lin -> alphas ----------------
// Block = (T-strip of 64) x batch, 512 threads (one per channel), register sliding window.
__launch_bounds__(512)
__global__ void conv_ln_logit_kernel(const float* __restrict__ dw_w, const float* __restrict__ dw_b,
                                     const float* __restrict__ ln_g, const float* __restrict__ ln_b,
                                     const int* __restrict__ x_lens)
{
    const int ch = threadIdx.x;
    const int b  = blockIdx.y;
    const int t0 = blockIdx.x * 64;
    const int lane = ch & 31, wid = ch >> 5;
    __shared__ float r1[16], r2[16], r3s[16];

    float wk[15];
    #pragma unroll
    for (int k = 0; k < 15; k++) wk[k] = dw_w[ch*Kk + k];
    const float bias = dw_b[ch];
    const float gam  = ln_g[ch];
    const float bet  = ln_b[ch];
    const float weff = d_weff[ch];
    const float beff = d_beff;
    const int   len  = x_lens[b];

    const float* gb = d_g + (size_t)b*Tt*Hh + ch;

    float win[15];
    #pragma unroll
    for (int k = 0; k < 14; k++) {
        int tg = t0 - 14 + k;
        win[k] = (tg >= 0) ? gb[(size_t)tg*Hh] : 0.0f;
    }

    for (int t = 0; t < 64; t++) {
        win[14] = gb[(size_t)(t0 + t)*Hh];
        float c = bias;
        #pragma unroll
        for (int k = 0; k < 15; k++) c = fmaf(win[k], wk[k], c);
        #pragma unroll
        for (int k = 0; k < 14; k++) win[k] = win[k+1];

        // block reduce sum & sumsq
        float s1 = wred(c);
        float s2 = wred(c*c);
        if (lane == 0) { r1[wid] = s1; r2[wid] = s2; }
        __syncthreads();
        if (wid == 0) {
            float a  = (lane < 16) ? r1[lane] : 0.0f;
            float d2 = (lane < 16) ? r2[lane] : 0.0f;
            a  = wred(a);
            d2 = wred(d2);
            if (lane == 0) { r1[0] = a; r2[0] = d2; }
        }
        __syncthreads();
        float mean = r1[0] * (1.0f/512.0f);
        float var  = r2[0] * (1.0f/512.0f) - mean*mean;
        float y  = (c - mean) * rsqrtf(var + 1e-5f) * gam + bet;
        float sw = y * sigm(y);
        float p  = wred(sw * weff);
        if (lane == 0) r3s[wid] = p;
        __syncthreads();
        if (wid == 0) {
            float a = (lane < 16) ? r3s[lane] : 0.0f;
            a = wred(a);
            if (lane == 0 && ch == 0) {
                float logit = a + beff;
                int tg = t0 + t;
                d_alphas[b*Tt + tg] = (tg < len) ? sigm(logit) : 0.0f;
            }
        }
        __syncthreads();
    }
}

// ---------------- kernel 3: per-batch serial CIF scan (exact reference arithmetic) ----------------
__global__ void scan_kernel()
{
    __shared__ float sa[Tt];  // 8KB
    const int b = blockIdx.x;
    for (int i = threadIdx.x; i < Tt; i += blockDim.x) sa[i] = d_alphas[b*Tt + i];
    __syncthreads();
    if (threadIdx.x == 0) {
        float integ = 0.0f, psum = 0.0f;
        int j = 0;
        for (int t = 0; t < Tt; t++) {
            float a = sa[t];
            psum += a;
            float dist = 1.0f - integ;   // FIRE_TH - integrate (pre-add)
            integ = integ + a;           // same op order as reference
            if (integ >= 1.0f) {
                d_fire_t[b*Tt + j] = t;
                d_dist  [b*Tt + j] = dist;
                d_remain[b*Tt + j] = a - dist;
                integ -= 1.0f;
                j++;
            }
        }
        d_nfires[b] = j;
        d_ptn[b] = psum;
    }
}

// ---------------- kernel 4: write all outputs (fired rows, token counts, flipped rows) ----------------
// Every output element written exactly once (d_out is poisoned).
__launch_bounds__(128)
__global__ void output_kernel(const float* __restrict__ x, float* __restrict__ out)
{
    const int b   = blockIdx.y;
    const int j   = blockIdx.x;
    const int tid = threadIdx.x;     // 128 threads, 4 channels each
    float* outF = out;
    float* outP = out + (size_t)Bb*Tt*Hh;
    float* outR = outP + Bb;

    if (j == 0 && tid == 0) outP[b] = d_ptn[b];

    float4 acc = make_float4(0.0f, 0.0f, 0.0f, 0.0f);
    const int nf = d_nfires[b];

    if (j < nf) {
        const float* xb = x + (size_t)b*Tt*Hh + tid*4;
        const int tEnd = d_fire_t[b*Tt + j];
        int t;
        if (j > 0) {
            int   tPrev = d_fire_t[b*Tt + j - 1];
            float wl    = d_remain[b*Tt + j - 1];
            float4 v = *(const float4*)(xb + (size_t)tPrev*Hh);
            acc.x = wl*v.x; acc.y = wl*v.y; acc.z = wl*v.z; acc.w = wl*v.w;
            t = tPrev + 1;
        } else {
            t = 0;
        }
        for (; t < tEnd; t++) {
            float w = d_alphas[b*Tt + t];
            float4 v = *(const float4*)(xb + (size_t)t*Hh);
            acc.x = fmaf(w, v.x, acc.x); acc.y = fmaf(w, v.y, acc.y);
            acc.z = fmaf(w, v.z, acc.z); acc.w = fmaf(w, v.w, acc.w);
        }
        float wd = d_dist[b*Tt + j];
        float4 v = *(const float4*)(xb + (size_t)tEnd*Hh);
        acc.x = fmaf(wd, v.x, acc.x); acc.y = fmaf(wd, v.y, acc.y);
        acc.z = fmaf(wd, v.z, acc.z); acc.w = fmaf(wd, v.w, acc.w);
    }

    *(float4*)(outF + ((size_t)b*Tt + j)*Hh + tid*4) = acc;
    // flipped along H: element ch -> H-1-ch
    *(float4*)(outR + ((size_t)b*Tt + j)*Hh + (Hh - 4 - tid*4)) =
        make_float4(acc.w, acc.z, acc.y, acc.x);
}

// ---------------- launch ----------------
extern "C" void kernel_launch(void* const* d_in, const int* in_sizes, int n_in,
                              void* d_out, int out_size)
{
    const float* x      = (const float*)d_in[0];
    const int*   x_lens = (const int*)  d_in[1];
    const float* pw1_w  = (const float*)d_in[2];
    const float* pw1_b  = (const float*)d_in[3];
    const float* dw_w   = (const float*)d_in[4];
    const float* dw_b   = (const float*)d_in[5];
    const float* ln_g   = (const float*)d_in[6];
    const float* ln_b   = (const float*)d_in[7];
    const float* pw2_w  = (const float*)d_in[8];
    const float* pw2_b  = (const float*)d_in[9];
    const float* lin_w  = (const float*)d_in[10];
    const float* lin_b  = (const float*)d_in[11];
    float* out = (float*)d_out;

    weff_kernel<<<1, Hh>>>(pw2_w, pw2_b, lin_w, lin_b);
    gemm_glu_kernel<<<dim3(BT/128, Hh/64), 256>>>(x, pw1_w, pw1_b);
    conv_ln_logit_kernel<<<dim3(Tt/64, Bb), Hh>>>(dw_w, dw_b, ln_g, ln_b, x_lens);
    scan_kernel<<<Bb, 256>>>();
    output_kernel<<<dim3(Tt, Bb), 128>>>(x, out);
}